// round 16
// baseline (speedup 1.0000x reference)
#include <cuda_runtime.h>
#include <cuda_fp16.h>
#include <math.h>
#include <stdint.h>

// ---------------- problem constants (shape-specialized) ----------------
#define B_   4
#define NP   8192
#define NI   1024
#define DP   512
#define DI   768
#define HH   512
#define DO   512
#define NQ   (B_ * NP)        // 32768 query rows
#define NIMG (B_ * NI)        // 4096 image rows
#define XDIM (DP + DO)        // 1024 concat dim
#define KNN_K 3
#define EPS_ 1e-6f

// ---------------- device scratch (static; no allocations allowed) ------
__device__ __half g_P  [(size_t)NQ * DP];       // 32 MB fp16 point_token
__device__ __half g_Gh [(size_t)NQ * HH];       // 32 MB
__device__ __half g_Dh [(size_t)NQ * HH];       // 32 MB
__device__ __half g_I  [(size_t)NIMG * DI];     //  6 MB
__device__ __half g_Hi [(size_t)NIMG * HH];     //  4 MB
__device__ __half g_ifeat[(size_t)NIMG * DO];   //  4 MB
__device__ __half g_Gg [(size_t)NIMG * HH];     //  4 MB  F @ gateWa^T
__device__ __half g_Gd [(size_t)NIMG * HH];     //  4 MB  F @ deltaWa^T
__device__ int4   g_selI[NQ];                   // 512 KB absolute G-rows
__device__ float4 g_selW[NQ];                   // 512 KB weights
__device__ float4 g_cand[B_ * NI];              // 64 KB packed candidates
__device__ float  g_zeroB[HH];                  // zero bias (static zero-init)
// transposed weights, layout (N, K) K-major, fp16
__device__ __half g_iw1[(size_t)HH * DI];
__device__ __half g_iw2[(size_t)DO * HH];
__device__ __half g_gw1[(size_t)HH * XDIM];
__device__ __half g_gw2[(size_t)DO * HH];
__device__ __half g_dw1[(size_t)HH * XDIM];
__device__ __half g_dw2[(size_t)DO * HH];

// ---------------- helpers ----------------------------------------------
__device__ __forceinline__ uint32_t smem_u32_of(const void* p) {
    uint32_t a;
    asm("{ .reg .u64 t; cvta.to.shared.u64 t, %1; cvt.u32.u64 %0, t; }" : "=r"(a) : "l"(p));
    return a;
}

#define CP_ASYNC16(dst, src) \
    asm volatile("cp.async.cg.shared.global [%0], [%1], 16;" :: "r"(dst), "l"(src))
#define CP_COMMIT() asm volatile("cp.async.commit_group;" ::: "memory")
#define CP_WAIT2()  asm volatile("cp.async.wait_group 2;" ::: "memory")

#define LDSM_X4(r0, r1, r2, r3, addr) \
    asm volatile("ldmatrix.sync.aligned.m8n8.x4.shared.b16 {%0,%1,%2,%3}, [%4];" \
        : "=r"(r0), "=r"(r1), "=r"(r2), "=r"(r3) : "r"(addr))

#define MMA_F16(d, a, b0v, b1v)                                                \
    asm volatile("mma.sync.aligned.m16n8k16.row.col.f32.f16.f16.f32 "          \
        "{%0,%1,%2,%3}, {%4,%5,%6,%7}, {%8,%9}, {%0,%1,%2,%3};"                \
        : "+f"((d)[0]), "+f"((d)[1]), "+f"((d)[2]), "+f"((d)[3])               \
        : "r"((a)[0]), "r"((a)[1]), "r"((a)[2]), "r"((a)[3]),                  \
          "r"(b0v), "r"(b1v))

// ---------------- prep: transpose + cvt(image) + cvt(point) + cand ------
struct TS6 {
    const float* W[6];
    __half* T[6];
    int K[6];
    int N[6];
    int start[7];
    const float* img_src;   __half* img_dst;
    const float* pt_src;    __half* pt_dst;
    const float* coord;
    const void* mask_raw;
};
#define IMG_ELEMS2 ((size_t)NIMG * DI / 2)
#define PT_ELEMS2  ((size_t)NQ * DP / 2)
#define CVT_PER_BLOCK (1024 * 8)
#define IMG_BLOCKS ((IMG_ELEMS2 + CVT_PER_BLOCK - 1) / CVT_PER_BLOCK)
#define PT_BLOCKS  ((PT_ELEMS2 + CVT_PER_BLOCK - 1) / CVT_PER_BLOCK)

__device__ __forceinline__ void cvt_range(const float* src, __half* dst,
                                          size_t n2, size_t cb, int t) {
    size_t base = cb * CVT_PER_BLOCK + t;
#pragma unroll
    for (int r = 0; r < 8; r++) {
        size_t i = base + (size_t)r * 1024;
        if (i < n2) {
            float2 v = ((const float2*)src)[i];
            ((__half2*)dst)[i] = __floats2half2_rn(v.x, v.y);
        }
    }
}

__global__ void prep_all_kernel(TS6 e) {
    int bx = blockIdx.x;
    const int img_end = e.start[6] + (int)IMG_BLOCKS;
    const int pt_end  = img_end + (int)PT_BLOCKS;
    const int t = threadIdx.y * 32 + threadIdx.x;
    if (bx >= pt_end) {
        const int b = bx - pt_end;
        const int i = t;
        const float INF = __int_as_float(0x7f800000);
        const unsigned int* mw = (const unsigned int*)e.mask_raw;
        bool floatHit = false, multiByte = false;
#pragma unroll
        for (int k = 0; k < 16; k++) {
            unsigned int v = mw[k];
            if (v == 0x3F800000u) floatHit = true;
            else if (v & 0xFFFFFF00u) multiByte = true;
        }
        const int mode = floatHit ? 0 : (multiByte ? 2 : 1);
        const float* cc = e.coord + ((size_t)b * NI + i) * 3;
        float x = cc[0], y = cc[1], z = cc[2];
        const int gi = b * NI + i;
        float mv;
        if (mode == 0)      mv = ((const float*)e.mask_raw)[gi];
        else if (mode == 1) mv = (float)((const int*)e.mask_raw)[gi];
        else                mv = (float)((const unsigned char*)e.mask_raw)[gi];
        float ss = x * x + y * y + z * z;
        if (mv == 0.0f) ss = INF;
        g_cand[gi] = make_float4(x, y, z, ss);
        return;
    }
    if (bx >= img_end) { cvt_range(e.pt_src, e.pt_dst, PT_ELEMS2, bx - img_end, t); return; }
    if (bx >= e.start[6]) { cvt_range(e.img_src, e.img_dst, IMG_ELEMS2, bx - e.start[6], t); return; }
    __shared__ float tt[32][33];
    int m = 0;
    while (bx >= e.start[m + 1]) m++;
    const int local = bx - e.start[m];
    const int K = e.K[m], N = e.N[m];
    const int nt = N >> 5;
    const int n0 = (local % nt) << 5;
    const int k0 = (local / nt) << 5;
    const int tx = threadIdx.x, ty = threadIdx.y;
    tt[ty][tx] = e.W[m][(size_t)(k0 + ty) * N + n0 + tx];
    __syncthreads();
    e.T[m][(size_t)(n0 + ty) * K + k0 + tx] = __float2half_rn(tt[tx][ty]);
}

// ---------------- mma.sync fp16 GEMM, K-chunk 64, M tile templated ------
#define W_TILE_B 16384
template <int MT> struct GemmDims {
    static constexpr int A_TILE_B = MT * 32 * 128;
    static constexpr int STAGE_B  = A_TILE_B + W_TILE_B;
    static constexpr int SMEM     = 3 * STAGE_B;
    static constexpr int CTA_M    = 32 * MT;
};

struct FragCtx {
    uint32_t sbase;
    int tid, wm, wn;
    int a_row_in, a_kb, b_n_in, b_kb;
};

__device__ __forceinline__ FragCtx make_ctx(const char* smem) {
    FragCtx fc;
    fc.sbase = smem_u32_of(smem);
    fc.tid = threadIdx.x;
    const int wid = fc.tid >> 5;
    const int lane = fc.tid & 31;
    fc.wm = wid & 1;
    fc.wn = wid >> 1;
    fc.a_row_in = lane & 15;
    fc.a_kb = lane >> 4;
    fc.b_n_in = ((lane >> 4) << 3) + (lane & 7);
    fc.b_kb = (lane >> 3) & 1;
    return fc;
}

// W row stride = ldw (allows column-slice views of transposed weights)
template <int MT>
__device__ __forceinline__ void gemm_kloop(const FragCtx& fc,
                                           const __half* __restrict__ At,
                                           const __half* __restrict__ Wt,
                                           int Kd, int ldw, float acc[MT][4][4])
{
    constexpr int ATB = GemmDims<MT>::A_TILE_B;
    constexpr int STB = GemmDims<MT>::STAGE_B;
    const int nch = Kd >> 6;
    auto fill = [&](int ck) {
        const int k0 = ck << 6;
        const uint32_t st = fc.sbase + (ck % 3) * STB;
#pragma unroll
        for (int it = 0; it < MT; it++) {             // A: 32*MT rows
            int i = fc.tid + (it << 8);
            int row = i >> 3, cc = i & 7;
            uint32_t soff = row * 128 + (((cc ^ row) & 7) << 4);
            size_t goff = (size_t)row * Kd + k0 + cc * 8;
            CP_ASYNC16(st + soff, At + goff);
        }
#pragma unroll
        for (int it = 0; it < 4; it++) {              // W: 128 rows
            int i = fc.tid + (it << 8);
            int row = i >> 3, cc = i & 7;
            uint32_t soff = ATB + row * 128 + (((cc ^ row) & 7) << 4);
            size_t goff = (size_t)row * ldw + k0 + cc * 8;
            CP_ASYNC16(st + soff, Wt + goff);
        }
    };

    fill(0); CP_COMMIT();
    fill(1); CP_COMMIT();

    for (int c = 0; c < nch; c++) {
        if (c + 2 < nch) fill(c + 2);
        CP_COMMIT();
        CP_WAIT2();
        __syncthreads();

        const uint32_t stg = fc.sbase + (c % 3) * STB;
        const uint32_t sA = stg;
        const uint32_t sW = stg + ATB;

#pragma unroll
        for (int s = 0; s < 4; s++) {
            uint32_t bf[2][4];
#pragma unroll
            for (int np = 0; np < 2; np++) {
                int n = fc.wn * 32 + np * 16 + fc.b_n_in;
                int cc = (s << 1) + fc.b_kb;
                uint32_t bd = sW + n * 128 + (((cc ^ n) & 7) << 4);
                LDSM_X4(bf[np][0], bf[np][1], bf[np][2], bf[np][3], bd);
            }
#pragma unroll
            for (int mt = 0; mt < MT; mt++) {
                int row = fc.wm * (16 * MT) + mt * 16 + fc.a_row_in;
                int cc = (s << 1) + fc.a_kb;
                uint32_t af[4];
                uint32_t ad = sA + row * 128 + (((cc ^ row) & 7) << 4);
                LDSM_X4(af[0], af[1], af[2], af[3], ad);
#pragma unroll
                for (int nt = 0; nt < 4; nt++) {
                    uint32_t b0 = bf[nt >> 1][(nt & 1) * 2];
                    uint32_t b1 = bf[nt >> 1][(nt & 1) * 2 + 1];
                    MMA_F16(acc[mt][nt], af, b0, b1);
                }
            }
        }
        __syncthreads();
    }
}

// MODE 0 = bias+relu, 1 = bias only, 3 = bias + epilogue-gathered base + relu
template <int MT, int MODE, bool DUAL>
__global__ void __launch_bounds__(256, 2)
gemm_mma_kernel(const __half* __restrict__ A,
                const __half* __restrict__ W1,    // (N, *) K-major fp16
                const __half* __restrict__ W2,
                const float* __restrict__ bias1,
                const float* __restrict__ bias2,
                const __half* __restrict__ base1, // MODE 3: G table (NIMG, HH)
                const __half* __restrict__ base2,
                __half* __restrict__ Ch1,
                __half* __restrict__ Ch2,
                int Kd, int ldw, int Ncols, int nhalf)
{
    extern __shared__ char smem[];
    FragCtx fc = make_ctx(smem);
    const int lane = threadIdx.x & 31;

    int bxn = blockIdx.x;
    const __half* Wsel = W1;
    const float* bias = bias1;
    const __half* Gt = base1;
    __half* Ch = Ch1;
    if (DUAL && bxn >= nhalf) {
        bxn -= nhalf;
        Wsel = W2; bias = bias2; Gt = base2; Ch = Ch2;
    }

    const __half* At = A + (size_t)blockIdx.y * GemmDims<MT>::CTA_M * Kd;
    const __half* Wt = Wsel + (size_t)bxn * 128 * ldw;

    float acc[MT][4][4];
#pragma unroll
    for (int i = 0; i < MT; i++)
#pragma unroll
        for (int j = 0; j < 4; j++)
#pragma unroll
            for (int r = 0; r < 4; r++) acc[i][j][r] = 0.0f;

    gemm_kloop<MT>(fc, At, Wt, Kd, ldw, acc);

    const int rbase = blockIdx.y * GemmDims<MT>::CTA_M + fc.wm * (16 * MT) + (lane >> 2);
    const int cbase = bxn * 128 + fc.wn * 32 + ((lane & 3) << 1);
#pragma unroll
    for (int mt = 0; mt < MT; mt++) {
#pragma unroll
        for (int half = 0; half < 2; half++) {
            const int row = rbase + mt * 16 + half * 8;
            int4 si; float4 sw;
            if (MODE == 3) { si = g_selI[row]; sw = g_selW[row]; }
#pragma unroll
            for (int nt = 0; nt < 4; nt++) {
                const int col = cbase + nt * 8;
                float v0 = acc[mt][nt][half * 2 + 0] + bias[col];
                float v1 = acc[mt][nt][half * 2 + 1] + bias[col + 1];
                if (MODE == 3) {
                    float2 f0 = __half22float2(*(const __half2*)(Gt + (size_t)si.x * HH + col));
                    float2 f1 = __half22float2(*(const __half2*)(Gt + (size_t)si.y * HH + col));
                    float2 f2 = __half22float2(*(const __half2*)(Gt + (size_t)si.z * HH + col));
                    v0 += sw.x * f0.x + sw.y * f1.x + sw.z * f2.x;
                    v1 += sw.x * f0.y + sw.y * f1.y + sw.z * f2.y;
                }
                if (MODE == 0 || MODE == 3) { v0 = fmaxf(v0, 0.0f); v1 = fmaxf(v1, 0.0f); }
                *(__half2*)(Ch + (size_t)row * Ncols + col) = __floats2half2_rn(v0, v1);
            }
        }
    }
}

// ---------------- fused gate-L2 + delta-L2 + sigmoid + residual ----------
__global__ void __launch_bounds__(256, 1)
gemm_fused2_kernel(const __half* __restrict__ Gh,
                   const __half* __restrict__ Dh,
                   const __half* __restrict__ Wg,   // (DO, HH) K-major
                   const __half* __restrict__ Wd,
                   const float* __restrict__ bg,
                   const float* __restrict__ bdl,
                   const float* __restrict__ pointp,
                   float* __restrict__ out)
{
    extern __shared__ char smem[];
    FragCtx fc = make_ctx(smem);
    const int lane = threadIdx.x & 31;

    float acc[4][4][4];
#pragma unroll
    for (int i = 0; i < 4; i++)
#pragma unroll
        for (int j = 0; j < 4; j++)
#pragma unroll
            for (int r = 0; r < 4; r++) acc[i][j][r] = 0.0f;

    // phase A: gate logits
    gemm_kloop<4>(fc, Gh + (size_t)blockIdx.y * 128 * HH,
                      Wg + (size_t)blockIdx.x * 128 * HH, HH, HH, acc);

    const int rbase = blockIdx.y * 128 + fc.wm * 64 + (lane >> 2);
    const int cbase = blockIdx.x * 128 + fc.wn * 32 + ((lane & 3) << 1);

    uint32_t sig[4][2][4];
#pragma unroll
    for (int mt = 0; mt < 4; mt++)
#pragma unroll
        for (int half = 0; half < 2; half++)
#pragma unroll
            for (int nt = 0; nt < 4; nt++) {
                const int col = cbase + nt * 8;
                float g0 = acc[mt][nt][half * 2 + 0] + bg[col];
                float g1 = acc[mt][nt][half * 2 + 1] + bg[col + 1];
                float s0 = 1.0f / (1.0f + expf(-g0));
                float s1 = 1.0f / (1.0f + expf(-g1));
                __half2 h = __floats2half2_rn(s0, s1);
                sig[mt][half][nt] = *(uint32_t*)&h;
                acc[mt][nt][half * 2 + 0] = 0.0f;
                acc[mt][nt][half * 2 + 1] = 0.0f;
            }

    // phase B: delta logits
    gemm_kloop<4>(fc, Dh + (size_t)blockIdx.y * 128 * HH,
                      Wd + (size_t)blockIdx.x * 128 * HH, HH, HH, acc);

    // epilogue: out = point + sigmoid(gate) * delta
#pragma unroll
    for (int mt = 0; mt < 4; mt++) {
#pragma unroll
        for (int half = 0; half < 2; half++) {
            const int row = rbase + mt * 16 + half * 8;
#pragma unroll
            for (int nt = 0; nt < 4; nt++) {
                const int col = cbase + nt * 8;
                size_t o = (size_t)row * DO + col;
                float v0 = acc[mt][nt][half * 2 + 0] + bdl[col];
                float v1 = acc[mt][nt][half * 2 + 1] + bdl[col + 1];
                __half2 hs = *(__half2*)&sig[mt][half][nt];
                float2 s = __half22float2(hs);
                float2 v;
                v.x = pointp[o]     + s.x * v0;
                v.y = pointp[o + 1] + s.y * v1;
                *(float2*)(out + o) = v;
            }
        }
    }
}

// ---------------- KNN select only (top-3 + weights -> selI/selW) ---------
__global__ __launch_bounds__(256)
void knn_select_kernel(const float* __restrict__ patch_center)   // (B,Np,3)
{
    __shared__ float4 scand[NI];
    const int b = blockIdx.y;
    const float INF = __int_as_float(0x7f800000);

    for (int i = threadIdx.x; i < NI; i += blockDim.x)
        scand[i] = g_cand[b * NI + i];
    __syncthreads();

    const int warp = threadIdx.x >> 5;
    const int lane = threadIdx.x & 31;
    const int p = blockIdx.x * 8 + warp;

    const float* q = patch_center + ((size_t)b * NP + p) * 3;
    const float qx = q[0], qy = q[1], qz = q[2];
    const float qs = qx * qx + qy * qy + qz * qz;
    const float nx = -2.0f * qx, ny = -2.0f * qy, nz = -2.0f * qz;

    float bd0 = INF, bd1 = INF, bd2 = INF;
    int   bi0 = -1,  bi1 = -1,  bi2 = -1;

#pragma unroll 4
    for (int it = 0; it < NI / 32; it++) {
        int c = it * 32 + lane;
        float4 cd = scand[c];
        float d = fmaf(nx, cd.x, fmaf(ny, cd.y, fmaf(nz, cd.z, qs + cd.w)));
        if (d < bd2) {
            if (d < bd1) {
                bd2 = bd1; bi2 = bi1;
                if (d < bd0) { bd1 = bd0; bi1 = bi0; bd0 = d; bi0 = c; }
                else         { bd1 = d;   bi1 = c; }
            } else { bd2 = d; bi2 = c; }
        }
    }

    float selD[KNN_K]; int selI[KNN_K];
    int ptr = 0;
#pragma unroll
    for (int r = 0; r < KNN_K; r++) {
        float cand = (ptr == 0) ? bd0 : (ptr == 1) ? bd1 : (ptr == 2) ? bd2 : INF;
        int   ci   = (ptr == 0) ? bi0 : (ptr == 1) ? bi1 : (ptr == 2) ? bi2 : -1;
        float m = cand;
#pragma unroll
        for (int o = 16; o > 0; o >>= 1) m = fminf(m, __shfl_xor_sync(0xffffffffu, m, o));
        unsigned ball = __ballot_sync(0xffffffffu, cand == m);
        int owner = __ffs(ball) - 1;
        selD[r] = m;
        selI[r] = __shfl_sync(0xffffffffu, ci, owner);
        if (lane == owner) ptr++;
        ptr = min(ptr, 3);
    }

    if (lane == 0) {
        float w[KNN_K], wsum = 0.0f;
#pragma unroll
        for (int r = 0; r < KNN_K; r++) {
            float dist = sqrtf(fmaxf(selD[r], 0.0f));
            w[r] = (selI[r] >= 0) ? (1.0f / fmaxf(dist, EPS_)) : 0.0f;
            wsum += w[r];
        }
        float inv = 1.0f / fmaxf(wsum, EPS_);
#pragma unroll
        for (int r = 0; r < KNN_K; r++) {
            w[r] *= inv;
            if (selI[r] < 0) selI[r] = 0;
        }
        const size_t row = (size_t)b * NP + p;
        // store absolute G-table rows (b*NI + idx)
        g_selI[row] = make_int4(b * NI + selI[0], b * NI + selI[1], b * NI + selI[2], 0);
        g_selW[row] = make_float4(w[0], w[1], w[2], 0.0f);
    }
}

// ---------------- launch --------------------------------------------------
extern "C" void kernel_launch(void* const* d_in, const int* in_sizes, int n_in,
                              void* d_out, int out_size)
{
    const float* point_token  = (const float*)d_in[0];
    const float* patch_center = (const float*)d_in[1];
    const float* image_token  = (const float*)d_in[2];
    const float* image_coord  = (const float*)d_in[3];
    const void*  mask_raw     =               d_in[4];
    const float* img_w1  = (const float*)d_in[5];
    const float* img_b1  = (const float*)d_in[6];
    const float* img_w2  = (const float*)d_in[7];
    const float* img_b2  = (const float*)d_in[8];
    const float* gate_w1 = (const float*)d_in[9];
    const float* gate_b1 = (const float*)d_in[10];
    const float* gate_w2 = (const float*)d_in[11];
    const float* gate_b2 = (const float*)d_in[12];
    const float* delta_w1 = (const float*)d_in[13];
    const float* delta_b1 = (const float*)d_in[14];
    const float* delta_w2 = (const float*)d_in[15];
    const float* delta_b2 = (const float*)d_in[16];
    float* out = (float*)d_out;

    __half *P, *Gh, *Dh, *I, *Hi, *ifeat, *Gg, *Gd;
    __half *iw1, *iw2, *gw1, *gw2, *dw1, *dw2;
    float *zeroB;
    cudaGetSymbolAddress((void**)&P,  g_P);
    cudaGetSymbolAddress((void**)&Gh, g_Gh);
    cudaGetSymbolAddress((void**)&Dh, g_Dh);
    cudaGetSymbolAddress((void**)&I,  g_I);
    cudaGetSymbolAddress((void**)&Hi, g_Hi);
    cudaGetSymbolAddress((void**)&ifeat, g_ifeat);
    cudaGetSymbolAddress((void**)&Gg, g_Gg);
    cudaGetSymbolAddress((void**)&Gd, g_Gd);
    cudaGetSymbolAddress((void**)&zeroB, g_zeroB);
    cudaGetSymbolAddress((void**)&iw1, g_iw1);
    cudaGetSymbolAddress((void**)&iw2, g_iw2);
    cudaGetSymbolAddress((void**)&gw1, g_gw1);
    cudaGetSymbolAddress((void**)&gw2, g_gw2);
    cudaGetSymbolAddress((void**)&dw1, g_dw1);
    cudaGetSymbolAddress((void**)&dw2, g_dw2);

    constexpr int SM4 = GemmDims<4>::SMEM;   // 96 KB
    constexpr int SM2 = GemmDims<2>::SMEM;   // 72 KB
    cudaFuncSetAttribute(gemm_mma_kernel<2, 0, false>, cudaFuncAttributeMaxDynamicSharedMemorySize, SM2);
    cudaFuncSetAttribute(gemm_mma_kernel<2, 1, false>, cudaFuncAttributeMaxDynamicSharedMemorySize, SM2);
    cudaFuncSetAttribute(gemm_mma_kernel<4, 1, true>,  cudaFuncAttributeMaxDynamicSharedMemorySize, SM4);
    cudaFuncSetAttribute(gemm_mma_kernel<4, 3, true>,  cudaFuncAttributeMaxDynamicSharedMemorySize, SM4);
    cudaFuncSetAttribute(gemm_fused2_kernel,           cudaFuncAttributeMaxDynamicSharedMemorySize, SM4);

    // 1. prep: transposes + cvt(image) + cvt(point) + candidate pack
    TS6 ts;
    ts.W[0] = img_w1;   ts.T[0] = iw1; ts.K[0] = DI;   ts.N[0] = HH;
    ts.W[1] = img_w2;   ts.T[1] = iw2; ts.K[1] = HH;   ts.N[1] = DO;
    ts.W[2] = gate_w1;  ts.T[2] = gw1; ts.K[2] = XDIM; ts.N[2] = HH;
    ts.W[3] = gate_w2;  ts.T[3] = gw2; ts.K[3] = HH;   ts.N[3] = DO;
    ts.W[4] = delta_w1; ts.T[4] = dw1; ts.K[4] = XDIM; ts.N[4] = HH;
    ts.W[5] = delta_w2; ts.T[5] = dw2; ts.K[5] = HH;   ts.N[5] = DO;
    ts.start[0] = 0;
    for (int i = 0; i < 6; i++)
        ts.start[i + 1] = ts.start[i] + (ts.N[i] / 32) * (ts.K[i] / 32);
    ts.img_src = image_token;  ts.img_dst = I;
    ts.pt_src  = point_token;  ts.pt_dst  = P;
    ts.coord = image_coord;
    ts.mask_raw = mask_raw;
    prep_all_kernel<<<ts.start[6] + (int)IMG_BLOCKS + (int)PT_BLOCKS + B_, dim3(32, 32)>>>(ts);

    // 2. image MLP
    gemm_mma_kernel<2, 0, false><<<dim3(HH / 128, NIMG / 64), 256, SM2>>>(
        I, iw1, nullptr, img_b1, nullptr, nullptr, nullptr, Hi, nullptr, DI, DI, HH, 0);
    gemm_mma_kernel<2, 1, false><<<dim3(DO / 128, NIMG / 64), 256, SM2>>>(
        Hi, iw2, nullptr, img_b2, nullptr, nullptr, nullptr, ifeat, nullptr, HH, HH, DO, 0);

    // 3. F-GEMMs: G_{g,d} = ifeat @ W_a^T  (W_a = cols 512.. of transposed W1)
    gemm_mma_kernel<4, 1, true><<<dim3(2 * HH / 128, NIMG / 128), 256, SM4>>>(
        ifeat, gw1 + DP, dw1 + DP, zeroB, zeroB, nullptr, nullptr,
        Gg, Gd, DO, XDIM, HH, HH / 128);

    // 4. KNN select (writes selI/selW only)
    knn_select_kernel<<<dim3(NP / 8, B_), 256>>>(patch_center);

    // 5. L1-dual: P @ W_p^T + bias + gathered G base, relu -> Gh/Dh (K=512)
    gemm_mma_kernel<4, 3, true><<<dim3(2 * HH / 128, NQ / 128), 256, SM4>>>(
        P, gw1, dw1, gate_b1, delta_b1, Gg, Gd,
        Gh, Dh, DP, XDIM, HH, HH / 128);

    // 6. fused gate-L2 + delta-L2 + sigmoid + residual -> out
    gemm_fused2_kernel<<<dim3(DO / 128, NQ / 128), 256, SM4>>>(
        Gh, Dh, gw2, dw2, gate_b2, delta_b2, point_token, out);
}

// round 17
// speedup vs baseline: 1.0411x; 1.0411x over previous
#include <cuda_runtime.h>
#include <cuda_fp16.h>
#include <math.h>
#include <stdint.h>

// ---------------- problem constants (shape-specialized) ----------------
#define B_   4
#define NP   8192
#define NI   1024
#define DP   512
#define DI   768
#define HH   512
#define DO   512
#define NQ   (B_ * NP)        // 32768 query rows
#define NIMG (B_ * NI)        // 4096 image rows
#define XDIM (DP + DO)        // 1024 concat dim
#define KNN_K 3
#define EPS_ 1e-6f

// ---------------- device scratch (static; no allocations allowed) ------
__device__ __half g_P  [(size_t)NQ * DP];       // 32 MB fp16 point_token
__device__ __half g_Gh [(size_t)NQ * HH];       // 32 MB
__device__ __half g_Dh [(size_t)NQ * HH];       // 32 MB
__device__ __half g_I  [(size_t)NIMG * DI];     //  6 MB
__device__ __half g_Hi [(size_t)NIMG * HH];     //  4 MB
__device__ __half g_ifeat[(size_t)NIMG * DO];   //  4 MB
__device__ __half g_Gg [(size_t)NIMG * HH];     //  4 MB  F @ gateWa^T
__device__ __half g_Gd [(size_t)NIMG * HH];     //  4 MB  F @ deltaWa^T
__device__ __half g_baseg[(size_t)NQ * HH];     // 32 MB  gathered gate base
__device__ __half g_based[(size_t)NQ * HH];     // 32 MB  gathered delta base
__device__ float4 g_cand[B_ * NI];              // 64 KB packed candidates
__device__ float  g_zeroB[HH];                  // zero bias (static zero-init)
// transposed weights, layout (N, K) K-major, fp16
__device__ __half g_iw1[(size_t)HH * DI];
__device__ __half g_iw2[(size_t)DO * HH];
__device__ __half g_gw1[(size_t)HH * XDIM];
__device__ __half g_gw2[(size_t)DO * HH];
__device__ __half g_dw1[(size_t)HH * XDIM];
__device__ __half g_dw2[(size_t)DO * HH];

// ---------------- helpers ----------------------------------------------
__device__ __forceinline__ uint32_t smem_u32_of(const void* p) {
    uint32_t a;
    asm("{ .reg .u64 t; cvta.to.shared.u64 t, %1; cvt.u32.u64 %0, t; }" : "=r"(a) : "l"(p));
    return a;
}

#define CP_ASYNC16(dst, src) \
    asm volatile("cp.async.cg.shared.global [%0], [%1], 16;" :: "r"(dst), "l"(src))
#define CP_COMMIT() asm volatile("cp.async.commit_group;" ::: "memory")
#define CP_WAIT2()  asm volatile("cp.async.wait_group 2;" ::: "memory")

#define LDSM_X4(r0, r1, r2, r3, addr) \
    asm volatile("ldmatrix.sync.aligned.m8n8.x4.shared.b16 {%0,%1,%2,%3}, [%4];" \
        : "=r"(r0), "=r"(r1), "=r"(r2), "=r"(r3) : "r"(addr))

#define MMA_F16(d, a, b0v, b1v)                                                \
    asm volatile("mma.sync.aligned.m16n8k16.row.col.f32.f16.f16.f32 "          \
        "{%0,%1,%2,%3}, {%4,%5,%6,%7}, {%8,%9}, {%0,%1,%2,%3};"                \
        : "+f"((d)[0]), "+f"((d)[1]), "+f"((d)[2]), "+f"((d)[3])               \
        : "r"((a)[0]), "r"((a)[1]), "r"((a)[2]), "r"((a)[3]),                  \
          "r"(b0v), "r"(b1v))

// ---------------- prep: transpose + cvt(image) + cvt(point) + cand ------
struct TS6 {
    const float* W[6];
    __half* T[6];
    int K[6];
    int N[6];
    int start[7];
    const float* img_src;   __half* img_dst;
    const float* pt_src;    __half* pt_dst;
    const float* coord;
    const void* mask_raw;
};
#define IMG_ELEMS2 ((size_t)NIMG * DI / 2)
#define PT_ELEMS2  ((size_t)NQ * DP / 2)
#define CVT_PER_BLOCK (1024 * 8)
#define IMG_BLOCKS ((IMG_ELEMS2 + CVT_PER_BLOCK - 1) / CVT_PER_BLOCK)
#define PT_BLOCKS  ((PT_ELEMS2 + CVT_PER_BLOCK - 1) / CVT_PER_BLOCK)

__device__ __forceinline__ void cvt_range(const float* src, __half* dst,
                                          size_t n2, size_t cb, int t) {
    size_t base = cb * CVT_PER_BLOCK + t;
#pragma unroll
    for (int r = 0; r < 8; r++) {
        size_t i = base + (size_t)r * 1024;
        if (i < n2) {
            float2 v = ((const float2*)src)[i];
            ((__half2*)dst)[i] = __floats2half2_rn(v.x, v.y);
        }
    }
}

__global__ void prep_all_kernel(TS6 e) {
    int bx = blockIdx.x;
    const int img_end = e.start[6] + (int)IMG_BLOCKS;
    const int pt_end  = img_end + (int)PT_BLOCKS;
    const int t = threadIdx.y * 32 + threadIdx.x;
    if (bx >= pt_end) {
        const int b = bx - pt_end;
        const int i = t;
        const float INF = __int_as_float(0x7f800000);
        const unsigned int* mw = (const unsigned int*)e.mask_raw;
        bool floatHit = false, multiByte = false;
#pragma unroll
        for (int k = 0; k < 16; k++) {
            unsigned int v = mw[k];
            if (v == 0x3F800000u) floatHit = true;
            else if (v & 0xFFFFFF00u) multiByte = true;
        }
        const int mode = floatHit ? 0 : (multiByte ? 2 : 1);
        const float* cc = e.coord + ((size_t)b * NI + i) * 3;
        float x = cc[0], y = cc[1], z = cc[2];
        const int gi = b * NI + i;
        float mv;
        if (mode == 0)      mv = ((const float*)e.mask_raw)[gi];
        else if (mode == 1) mv = (float)((const int*)e.mask_raw)[gi];
        else                mv = (float)((const unsigned char*)e.mask_raw)[gi];
        float ss = x * x + y * y + z * z;
        if (mv == 0.0f) ss = INF;
        g_cand[gi] = make_float4(x, y, z, ss);
        return;
    }
    if (bx >= img_end) { cvt_range(e.pt_src, e.pt_dst, PT_ELEMS2, bx - img_end, t); return; }
    if (bx >= e.start[6]) { cvt_range(e.img_src, e.img_dst, IMG_ELEMS2, bx - e.start[6], t); return; }
    __shared__ float tt[32][33];
    int m = 0;
    while (bx >= e.start[m + 1]) m++;
    const int local = bx - e.start[m];
    const int K = e.K[m], N = e.N[m];
    const int nt = N >> 5;
    const int n0 = (local % nt) << 5;
    const int k0 = (local / nt) << 5;
    const int tx = threadIdx.x, ty = threadIdx.y;
    tt[ty][tx] = e.W[m][(size_t)(k0 + ty) * N + n0 + tx];
    __syncthreads();
    e.T[m][(size_t)(n0 + ty) * K + k0 + tx] = __float2half_rn(tt[tx][ty]);
}

// ---------------- mma.sync fp16 GEMM, K-chunk 64, M tile templated ------
#define W_TILE_B 16384
template <int MT> struct GemmDims {
    static constexpr int A_TILE_B = MT * 32 * 128;
    static constexpr int STAGE_B  = A_TILE_B + W_TILE_B;
    static constexpr int SMEM     = 3 * STAGE_B;
    static constexpr int CTA_M    = 32 * MT;
};

struct FragCtx {
    uint32_t sbase;
    int tid, wm, wn;
    int a_row_in, a_kb, b_n_in, b_kb;
};

__device__ __forceinline__ FragCtx make_ctx(const char* smem) {
    FragCtx fc;
    fc.sbase = smem_u32_of(smem);
    fc.tid = threadIdx.x;
    const int wid = fc.tid >> 5;
    const int lane = fc.tid & 31;
    fc.wm = wid & 1;
    fc.wn = wid >> 1;
    fc.a_row_in = lane & 15;
    fc.a_kb = lane >> 4;
    fc.b_n_in = ((lane >> 4) << 3) + (lane & 7);
    fc.b_kb = (lane >> 3) & 1;
    return fc;
}

// W row stride = ldw (allows column-slice views of transposed weights)
template <int MT>
__device__ __forceinline__ void gemm_kloop(const FragCtx& fc,
                                           const __half* __restrict__ At,
                                           const __half* __restrict__ Wt,
                                           int Kd, int ldw, float acc[MT][4][4])
{
    constexpr int ATB = GemmDims<MT>::A_TILE_B;
    constexpr int STB = GemmDims<MT>::STAGE_B;
    const int nch = Kd >> 6;
    auto fill = [&](int ck) {
        const int k0 = ck << 6;
        const uint32_t st = fc.sbase + (ck % 3) * STB;
#pragma unroll
        for (int it = 0; it < MT; it++) {             // A: 32*MT rows
            int i = fc.tid + (it << 8);
            int row = i >> 3, cc = i & 7;
            uint32_t soff = row * 128 + (((cc ^ row) & 7) << 4);
            size_t goff = (size_t)row * Kd + k0 + cc * 8;
            CP_ASYNC16(st + soff, At + goff);
        }
#pragma unroll
        for (int it = 0; it < 4; it++) {              // W: 128 rows
            int i = fc.tid + (it << 8);
            int row = i >> 3, cc = i & 7;
            uint32_t soff = ATB + row * 128 + (((cc ^ row) & 7) << 4);
            size_t goff = (size_t)row * ldw + k0 + cc * 8;
            CP_ASYNC16(st + soff, Wt + goff);
        }
    };

    fill(0); CP_COMMIT();
    fill(1); CP_COMMIT();

    for (int c = 0; c < nch; c++) {
        if (c + 2 < nch) fill(c + 2);
        CP_COMMIT();
        CP_WAIT2();
        __syncthreads();

        const uint32_t stg = fc.sbase + (c % 3) * STB;
        const uint32_t sA = stg;
        const uint32_t sW = stg + ATB;

#pragma unroll
        for (int s = 0; s < 4; s++) {
            uint32_t bf[2][4];
#pragma unroll
            for (int np = 0; np < 2; np++) {
                int n = fc.wn * 32 + np * 16 + fc.b_n_in;
                int cc = (s << 1) + fc.b_kb;
                uint32_t bd = sW + n * 128 + (((cc ^ n) & 7) << 4);
                LDSM_X4(bf[np][0], bf[np][1], bf[np][2], bf[np][3], bd);
            }
#pragma unroll
            for (int mt = 0; mt < MT; mt++) {
                int row = fc.wm * (16 * MT) + mt * 16 + fc.a_row_in;
                int cc = (s << 1) + fc.a_kb;
                uint32_t af[4];
                uint32_t ad = sA + row * 128 + (((cc ^ row) & 7) << 4);
                LDSM_X4(af[0], af[1], af[2], af[3], ad);
#pragma unroll
                for (int nt = 0; nt < 4; nt++) {
                    uint32_t b0 = bf[nt >> 1][(nt & 1) * 2];
                    uint32_t b1 = bf[nt >> 1][(nt & 1) * 2 + 1];
                    MMA_F16(acc[mt][nt], af, b0, b1);
                }
            }
        }
        __syncthreads();
    }
}

// MODE 0 = bias+relu, 1 = bias only, 2 = bias + fp16 base + relu
template <int MT, int MODE, bool DUAL>
__global__ void __launch_bounds__(256, 2)
gemm_mma_kernel(const __half* __restrict__ A,
                const __half* __restrict__ W1,    // (N, *) K-major fp16
                const __half* __restrict__ W2,
                const float* __restrict__ bias1,
                const float* __restrict__ bias2,
                const __half* __restrict__ base1, // MODE 2
                const __half* __restrict__ base2,
                __half* __restrict__ Ch1,
                __half* __restrict__ Ch2,
                int Kd, int ldw, int Ncols, int nhalf)
{
    extern __shared__ char smem[];
    FragCtx fc = make_ctx(smem);
    const int lane = threadIdx.x & 31;

    int bxn = blockIdx.x;
    const __half* Wsel = W1;
    const float* bias = bias1;
    const __half* base = base1;
    __half* Ch = Ch1;
    if (DUAL && bxn >= nhalf) {
        bxn -= nhalf;
        Wsel = W2; bias = bias2; base = base2; Ch = Ch2;
    }

    const __half* At = A + (size_t)blockIdx.y * GemmDims<MT>::CTA_M * Kd;
    const __half* Wt = Wsel + (size_t)bxn * 128 * ldw;

    float acc[MT][4][4];
#pragma unroll
    for (int i = 0; i < MT; i++)
#pragma unroll
        for (int j = 0; j < 4; j++)
#pragma unroll
            for (int r = 0; r < 4; r++) acc[i][j][r] = 0.0f;

    gemm_kloop<MT>(fc, At, Wt, Kd, ldw, acc);

    const int rbase = blockIdx.y * GemmDims<MT>::CTA_M + fc.wm * (16 * MT) + (lane >> 2);
    const int cbase = bxn * 128 + fc.wn * 32 + ((lane & 3) << 1);
#pragma unroll
    for (int mt = 0; mt < MT; mt++) {
#pragma unroll
        for (int half = 0; half < 2; half++) {
            const int row = rbase + mt * 16 + half * 8;
#pragma unroll
            for (int nt = 0; nt < 4; nt++) {
                const int col = cbase + nt * 8;
                float v0 = acc[mt][nt][half * 2 + 0] + bias[col];
                float v1 = acc[mt][nt][half * 2 + 1] + bias[col + 1];
                if (MODE == 2) {
                    __half2 bz = *(const __half2*)(base + (size_t)row * Ncols + col);
                    float2 bf = __half22float2(bz);
                    v0 += bf.x; v1 += bf.y;
                }
                if (MODE == 0 || MODE == 2) { v0 = fmaxf(v0, 0.0f); v1 = fmaxf(v1, 0.0f); }
                *(__half2*)(Ch + (size_t)row * Ncols + col) = __floats2half2_rn(v0, v1);
            }
        }
    }
}

// ---------------- fused gate-L2 + delta-L2 + sigmoid + residual ----------
__global__ void __launch_bounds__(256, 1)
gemm_fused2_kernel(const __half* __restrict__ Gh,
                   const __half* __restrict__ Dh,
                   const __half* __restrict__ Wg,   // (DO, HH) K-major
                   const __half* __restrict__ Wd,
                   const float* __restrict__ bg,
                   const float* __restrict__ bdl,
                   const float* __restrict__ pointp,
                   float* __restrict__ out)
{
    extern __shared__ char smem[];
    FragCtx fc = make_ctx(smem);
    const int lane = threadIdx.x & 31;

    float acc[4][4][4];
#pragma unroll
    for (int i = 0; i < 4; i++)
#pragma unroll
        for (int j = 0; j < 4; j++)
#pragma unroll
            for (int r = 0; r < 4; r++) acc[i][j][r] = 0.0f;

    // phase A: gate logits
    gemm_kloop<4>(fc, Gh + (size_t)blockIdx.y * 128 * HH,
                      Wg + (size_t)blockIdx.x * 128 * HH, HH, HH, acc);

    const int rbase = blockIdx.y * 128 + fc.wm * 64 + (lane >> 2);
    const int cbase = blockIdx.x * 128 + fc.wn * 32 + ((lane & 3) << 1);

    uint32_t sig[4][2][4];
#pragma unroll
    for (int mt = 0; mt < 4; mt++)
#pragma unroll
        for (int half = 0; half < 2; half++)
#pragma unroll
            for (int nt = 0; nt < 4; nt++) {
                const int col = cbase + nt * 8;
                float g0 = acc[mt][nt][half * 2 + 0] + bg[col];
                float g1 = acc[mt][nt][half * 2 + 1] + bg[col + 1];
                float s0 = 1.0f / (1.0f + expf(-g0));
                float s1 = 1.0f / (1.0f + expf(-g1));
                __half2 h = __floats2half2_rn(s0, s1);
                sig[mt][half][nt] = *(uint32_t*)&h;
                acc[mt][nt][half * 2 + 0] = 0.0f;
                acc[mt][nt][half * 2 + 1] = 0.0f;
            }

    // phase B: delta logits
    gemm_kloop<4>(fc, Dh + (size_t)blockIdx.y * 128 * HH,
                      Wd + (size_t)blockIdx.x * 128 * HH, HH, HH, acc);

    // epilogue: out = point + sigmoid(gate) * delta
#pragma unroll
    for (int mt = 0; mt < 4; mt++) {
#pragma unroll
        for (int half = 0; half < 2; half++) {
            const int row = rbase + mt * 16 + half * 8;
#pragma unroll
            for (int nt = 0; nt < 4; nt++) {
                const int col = cbase + nt * 8;
                size_t o = (size_t)row * DO + col;
                float v0 = acc[mt][nt][half * 2 + 0] + bdl[col];
                float v1 = acc[mt][nt][half * 2 + 1] + bdl[col + 1];
                __half2 hs = *(__half2*)&sig[mt][half][nt];
                float2 s = __half22float2(hs);
                float2 v;
                v.x = pointp[o]     + s.x * v0;
                v.y = pointp[o + 1] + s.y * v1;
                *(float2*)(out + o) = v;
            }
        }
    }
}

// ---------------- KNN select + gathered base sum (vectorized) ------------
// Scan pre-packed candidates for top-3 + weights, then write
// base_g/base_d[row] = sum_k w_k * G{g,d}[b*NI + idx_k], int4-vectorized.
__global__ __launch_bounds__(256)
void knn_base_kernel(const float* __restrict__ patch_center)   // (B,Np,3)
{
    __shared__ float4 scand[NI];
    const int b = blockIdx.y;
    const float INF = __int_as_float(0x7f800000);

    for (int i = threadIdx.x; i < NI; i += blockDim.x)
        scand[i] = g_cand[b * NI + i];
    __syncthreads();

    const int warp = threadIdx.x >> 5;
    const int lane = threadIdx.x & 31;
    const int p = blockIdx.x * 8 + warp;

    const float* q = patch_center + ((size_t)b * NP + p) * 3;
    const float qx = q[0], qy = q[1], qz = q[2];
    const float qs = qx * qx + qy * qy + qz * qz;
    const float nx = -2.0f * qx, ny = -2.0f * qy, nz = -2.0f * qz;

    float bd0 = INF, bd1 = INF, bd2 = INF;
    int   bi0 = -1,  bi1 = -1,  bi2 = -1;

#pragma unroll 4
    for (int it = 0; it < NI / 32; it++) {
        int c = it * 32 + lane;
        float4 cd = scand[c];
        float d = fmaf(nx, cd.x, fmaf(ny, cd.y, fmaf(nz, cd.z, qs + cd.w)));
        if (d < bd2) {
            if (d < bd1) {
                bd2 = bd1; bi2 = bi1;
                if (d < bd0) { bd1 = bd0; bi1 = bi0; bd0 = d; bi0 = c; }
                else         { bd1 = d;   bi1 = c; }
            } else { bd2 = d; bi2 = c; }
        }
    }

    float selD[KNN_K]; int selI[KNN_K];
    int ptr = 0;
#pragma unroll
    for (int r = 0; r < KNN_K; r++) {
        float cand = (ptr == 0) ? bd0 : (ptr == 1) ? bd1 : (ptr == 2) ? bd2 : INF;
        int   ci   = (ptr == 0) ? bi0 : (ptr == 1) ? bi1 : (ptr == 2) ? bi2 : -1;
        float m = cand;
#pragma unroll
        for (int o = 16; o > 0; o >>= 1) m = fminf(m, __shfl_xor_sync(0xffffffffu, m, o));
        unsigned ball = __ballot_sync(0xffffffffu, cand == m);
        int owner = __ffs(ball) - 1;
        selD[r] = m;
        selI[r] = __shfl_sync(0xffffffffu, ci, owner);
        if (lane == owner) ptr++;
        ptr = min(ptr, 3);
    }

    float w[KNN_K], wsum = 0.0f;
#pragma unroll
    for (int r = 0; r < KNN_K; r++) {
        float dist = sqrtf(fmaxf(selD[r], 0.0f));
        w[r] = (selI[r] >= 0) ? (1.0f / fmaxf(dist, EPS_)) : 0.0f;
        wsum += w[r];
    }
    float inv = 1.0f / fmaxf(wsum, EPS_);
#pragma unroll
    for (int r = 0; r < KNN_K; r++) {
        w[r] *= inv;
        if (selI[r] < 0) selI[r] = 0;
    }

    const size_t row = (size_t)b * NP + p;
    const size_t r0 = (size_t)b * NI + selI[0];
    const size_t r1 = (size_t)b * NI + selI[1];
    const size_t r2 = (size_t)b * NI + selI[2];
    const __half* gg0 = g_Gg + r0 * HH;
    const __half* gg1 = g_Gg + r1 * HH;
    const __half* gg2 = g_Gg + r2 * HH;
    const __half* gd0 = g_Gd + r0 * HH;
    const __half* gd1 = g_Gd + r1 * HH;
    const __half* gd2 = g_Gd + r2 * HH;
    __half* bg = g_baseg + row * HH;
    __half* bd = g_based + row * HH;

    // int4-vectorized weighted sum: 8 halfs per lane per iteration
#pragma unroll
    for (int it = 0; it < HH / 256; it++) {
        const int c = it * 256 + lane * 8;
        {
            int4 a0 = *(const int4*)(gg0 + c);
            int4 a1 = *(const int4*)(gg1 + c);
            int4 a2 = *(const int4*)(gg2 + c);
            const __half2* p0 = (const __half2*)&a0;
            const __half2* p1 = (const __half2*)&a1;
            const __half2* p2 = (const __half2*)&a2;
            __half2 o[4];
#pragma unroll
            for (int j = 0; j < 4; j++) {
                float2 f0 = __half22float2(p0[j]);
                float2 f1 = __half22float2(p1[j]);
                float2 f2 = __half22float2(p2[j]);
                o[j] = __floats2half2_rn(w[0] * f0.x + w[1] * f1.x + w[2] * f2.x,
                                         w[0] * f0.y + w[1] * f1.y + w[2] * f2.y);
            }
            *(int4*)(bg + c) = *(int4*)o;
        }
        {
            int4 a0 = *(const int4*)(gd0 + c);
            int4 a1 = *(const int4*)(gd1 + c);
            int4 a2 = *(const int4*)(gd2 + c);
            const __half2* p0 = (const __half2*)&a0;
            const __half2* p1 = (const __half2*)&a1;
            const __half2* p2 = (const __half2*)&a2;
            __half2 o[4];
#pragma unroll
            for (int j = 0; j < 4; j++) {
                float2 f0 = __half22float2(p0[j]);
                float2 f1 = __half22float2(p1[j]);
                float2 f2 = __half22float2(p2[j]);
                o[j] = __floats2half2_rn(w[0] * f0.x + w[1] * f1.x + w[2] * f2.x,
                                         w[0] * f0.y + w[1] * f1.y + w[2] * f2.y);
            }
            *(int4*)(bd + c) = *(int4*)o;
        }
    }
}

// ---------------- launch --------------------------------------------------
extern "C" void kernel_launch(void* const* d_in, const int* in_sizes, int n_in,
                              void* d_out, int out_size)
{
    const float* point_token  = (const float*)d_in[0];
    const float* patch_center = (const float*)d_in[1];
    const float* image_token  = (const float*)d_in[2];
    const float* image_coord  = (const float*)d_in[3];
    const void*  mask_raw     =               d_in[4];
    const float* img_w1  = (const float*)d_in[5];
    const float* img_b1  = (const float*)d_in[6];
    const float* img_w2  = (const float*)d_in[7];
    const float* img_b2  = (const float*)d_in[8];
    const float* gate_w1 = (const float*)d_in[9];
    const float* gate_b1 = (const float*)d_in[10];
    const float* gate_w2 = (const float*)d_in[11];
    const float* gate_b2 = (const float*)d_in[12];
    const float* delta_w1 = (const float*)d_in[13];
    const float* delta_b1 = (const float*)d_in[14];
    const float* delta_w2 = (const float*)d_in[15];
    const float* delta_b2 = (const float*)d_in[16];
    float* out = (float*)d_out;

    __half *P, *Gh, *Dh, *I, *Hi, *ifeat, *Gg, *Gd, *baseg, *based;
    __half *iw1, *iw2, *gw1, *gw2, *dw1, *dw2;
    float *zeroB;
    cudaGetSymbolAddress((void**)&P,  g_P);
    cudaGetSymbolAddress((void**)&Gh, g_Gh);
    cudaGetSymbolAddress((void**)&Dh, g_Dh);
    cudaGetSymbolAddress((void**)&I,  g_I);
    cudaGetSymbolAddress((void**)&Hi, g_Hi);
    cudaGetSymbolAddress((void**)&ifeat, g_ifeat);
    cudaGetSymbolAddress((void**)&Gg, g_Gg);
    cudaGetSymbolAddress((void**)&Gd, g_Gd);
    cudaGetSymbolAddress((void**)&baseg, g_baseg);
    cudaGetSymbolAddress((void**)&based, g_based);
    cudaGetSymbolAddress((void**)&zeroB, g_zeroB);
    cudaGetSymbolAddress((void**)&iw1, g_iw1);
    cudaGetSymbolAddress((void**)&iw2, g_iw2);
    cudaGetSymbolAddress((void**)&gw1, g_gw1);
    cudaGetSymbolAddress((void**)&gw2, g_gw2);
    cudaGetSymbolAddress((void**)&dw1, g_dw1);
    cudaGetSymbolAddress((void**)&dw2, g_dw2);

    constexpr int SM4 = GemmDims<4>::SMEM;   // 96 KB
    constexpr int SM2 = GemmDims<2>::SMEM;   // 72 KB
    cudaFuncSetAttribute(gemm_mma_kernel<2, 0, false>, cudaFuncAttributeMaxDynamicSharedMemorySize, SM2);
    cudaFuncSetAttribute(gemm_mma_kernel<2, 1, false>, cudaFuncAttributeMaxDynamicSharedMemorySize, SM2);
    cudaFuncSetAttribute(gemm_mma_kernel<4, 1, true>,  cudaFuncAttributeMaxDynamicSharedMemorySize, SM4);
    cudaFuncSetAttribute(gemm_mma_kernel<4, 2, true>,  cudaFuncAttributeMaxDynamicSharedMemorySize, SM4);
    cudaFuncSetAttribute(gemm_fused2_kernel,           cudaFuncAttributeMaxDynamicSharedMemorySize, SM4);

    // 1. prep: transposes + cvt(image) + cvt(point) + candidate pack
    TS6 ts;
    ts.W[0] = img_w1;   ts.T[0] = iw1; ts.K[0] = DI;   ts.N[0] = HH;
    ts.W[1] = img_w2;   ts.T[1] = iw2; ts.K[1] = HH;   ts.N[1] = DO;
    ts.W[2] = gate_w1;  ts.T[2] = gw1; ts.K[2] = XDIM; ts.N[2] = HH;
    ts.W[3] = gate_w2;  ts.T[3] = gw2; ts.K[3] = HH;   ts.N[3] = DO;
    ts.W[4] = delta_w1; ts.T[4] = dw1; ts.K[4] = XDIM; ts.N[4] = HH;
    ts.W[5] = delta_w2; ts.T[5] = dw2; ts.K[5] = HH;   ts.N[5] = DO;
    ts.start[0] = 0;
    for (int i = 0; i < 6; i++)
        ts.start[i + 1] = ts.start[i] + (ts.N[i] / 32) * (ts.K[i] / 32);
    ts.img_src = image_token;  ts.img_dst = I;
    ts.pt_src  = point_token;  ts.pt_dst  = P;
    ts.coord = image_coord;
    ts.mask_raw = mask_raw;
    prep_all_kernel<<<ts.start[6] + (int)IMG_BLOCKS + (int)PT_BLOCKS + B_, dim3(32, 32)>>>(ts);

    // 2. image MLP
    gemm_mma_kernel<2, 0, false><<<dim3(HH / 128, NIMG / 64), 256, SM2>>>(
        I, iw1, nullptr, img_b1, nullptr, nullptr, nullptr, Hi, nullptr, DI, DI, HH, 0);
    gemm_mma_kernel<2, 1, false><<<dim3(DO / 128, NIMG / 64), 256, SM2>>>(
        Hi, iw2, nullptr, img_b2, nullptr, nullptr, nullptr, ifeat, nullptr, HH, HH, DO, 0);

    // 3. F-GEMMs: G_{g,d} = ifeat @ W_a^T  (W_a = cols 512.. of transposed W1)
    gemm_mma_kernel<4, 1, true><<<dim3(2 * HH / 128, NIMG / 128), 256, SM4>>>(
        ifeat, gw1 + DP, dw1 + DP, zeroB, zeroB, nullptr, nullptr,
        Gg, Gd, DO, XDIM, HH, HH / 128);

    // 4. KNN select + gathered base sum (vectorized)
    knn_base_kernel<<<dim3(NP / 8, B_), 256>>>(patch_center);

    // 5. L1-dual: P @ W_p^T + base (+bias, relu) -> Gh/Dh   (K=512)
    gemm_mma_kernel<4, 2, true><<<dim3(2 * HH / 128, NQ / 128), 256, SM4>>>(
        P, gw1, dw1, gate_b1, delta_b1, baseg, based,
        Gh, Dh, DP, XDIM, HH, HH / 128);

    // 6. fused gate-L2 + delta-L2 + sigmoid + residual -> out
    gemm_fused2_kernel<<<dim3(DO / 128, NQ / 128), 256, SM4>>>(
        Gh, Dh, gw2, dw2, gate_b2, delta_b2, point_token, out);
}